// round 15
// baseline (speedup 1.0000x reference)
#include <cuda_runtime.h>
#include <cstdint>

// ---------------------------------------------------------------------------
// N=100000, 512 -> 16 -> 40, E=3.2M int32 edges.
// out = log_softmax( segsum(relu(segsum((xW1)[src])+b1)[src]) @ W2 + b2 )
// (W2 hoisted past the scatter by linearity of segment_sum.)
//
// R15: gemm1 = R10 layout with 2 rows/lane (was 4): acc 32->16 u64 regs,
// ~80 regs total -> 24 warps/SM (was 12). W-LDS doubles (~6us, noise).
// One-variable occupancy experiment against R10's latency-bound profile.
// RULE: __device__ globals only referenced in device code (ATS trap).
// ---------------------------------------------------------------------------

#define NNODES 100000
#define HID 16
#define NEDGES 3200000
#define NB_SCAN 391         // ceil(NNODES/256)

__device__ __align__(16) float g_h1 [NNODES * HID];   // x @ W1
__device__ __align__(16) float g_h2 [NNODES * HID];   // relu(segsum(h1)+b1)
__device__ __align__(16) float g_agg2[NNODES * HID];  // segsum(h2)
__device__ int g_cnt   [NNODES];
__device__ int g_rowptr[NNODES + 1];
__device__ int g_cursor[NNODES];
__device__ int g_esrc  [NEDGES];
__device__ int g_blksum[NB_SCAN];
__device__ int g_is64;

// packed f32x2 ops (PTX-only)
#define FMA_F32X2(d, a, b, c) \
    asm("fma.rn.f32x2 %0, %1, %2, %3;" : "=l"(d) : "l"(a), "l"(b), "l"(c))
#define ADD_F32X2(d, a, b) \
    asm("add.rn.f32x2 %0, %1, %2;" : "=l"(d) : "l"(a), "l"(b))
#define PACK2(d, s) \
    asm("mov.b64 %0, {%1, %1};" : "=l"(d) : "r"(__float_as_uint(s)))

// ---------------------------------------------------------------------------
__device__ __forceinline__ int edge_at(const int* ei, int idx, int E, int half) {
    if (g_is64) {
        const long long* ll = reinterpret_cast<const long long*>(ei);
        return (int)__ldg(ll + (size_t)half * E + idx);
    }
    return __ldg(ei + (size_t)half * E + idx);
}

// ---------------------------------------------------------------------------
// 1) prep: zero g_cnt; block 0 also detects int64 storage
// ---------------------------------------------------------------------------
__global__ void prep_kernel(const int* __restrict__ ei) {
    int i = blockIdx.x * blockDim.x + threadIdx.x;
    for (; i < NNODES; i += gridDim.x * blockDim.x) g_cnt[i] = 0;

    if (blockIdx.x == 0) {
        __shared__ int any_nonzero;
        if (threadIdx.x == 0) any_nonzero = 0;
        __syncthreads();
        int bad = 0;
        for (int w = 1 + 2 * threadIdx.x; w < 2048; w += 2 * blockDim.x)
            if (ei[w] != 0) bad = 1;
        if (bad) atomicOr(&any_nonzero, 1);
        __syncthreads();
        if (threadIdx.x == 0) g_is64 = (any_nonzero == 0) ? 1 : 0;
    }
}

// ---------------------------------------------------------------------------
// 2) histogram of destinations
// ---------------------------------------------------------------------------
__global__ void hist_kernel(const int* __restrict__ ei, int E) {
    int e = blockIdx.x * blockDim.x + threadIdx.x;
    if (e >= E) return;
    int d = edge_at(ei, e, E, 1);
    atomicAdd(&g_cnt[d], 1);
}

// ---------------------------------------------------------------------------
// 3) scan1: block-local exclusive scan; g_blksum[b] = block total
// ---------------------------------------------------------------------------
__global__ void scan1_kernel() {
    __shared__ int buf[2][256];
    int t = threadIdx.x, b = blockIdx.x;
    int i = b * 256 + t;
    int v = (i < NNODES) ? g_cnt[i] : 0;
    int cur = 0;
    buf[0][t] = v;
    __syncthreads();
#pragma unroll
    for (int off = 1; off < 256; off <<= 1) {
        int x = buf[cur][t];
        if (t >= off) x += buf[cur][t - off];
        buf[cur ^ 1][t] = x;
        cur ^= 1;
        __syncthreads();
    }
    int incl = buf[cur][t];
    if (i < NNODES) g_rowptr[i] = incl - v;
    if (t == 255) g_blksum[b] = incl;
}

// ---------------------------------------------------------------------------
// 4) h1 = x @ W1 — R10 layout, 2 rows/lane. warp = 8 rows;
//    lane = (rg = lane>>3 -> 2-row group, kg = lane&7 -> 64 k).
// ---------------------------------------------------------------------------
#define WS_STRIDE 1028
__global__ void __launch_bounds__(128) gemm1_kernel(const float* __restrict__ x,
                                                    const float* __restrict__ W1) {
    __shared__ __align__(16) float Ws[8 * WS_STRIDE];
    int tid = threadIdx.x;
    for (int i = tid; i < 8192; i += blockDim.x) {
        int k = i >> 4, j = i & 15;
        Ws[(k >> 6) * WS_STRIDE + (k & 63) * 16 + j] = W1[i];
    }
    __syncthreads();

    int lane = tid & 31;
    int wrp  = tid >> 5;
    int gw   = blockIdx.x * 4 + wrp;            // 12500 warps exactly
    if (gw >= NNODES / 8) return;
    int rg = lane >> 3;
    int kg = lane & 7;
    int row0 = gw * 8 + rg * 2;                 // 2 rows: row0, row0+1

    const float4* xv = reinterpret_cast<const float4*>(x);
    const float4* wsv = reinterpret_cast<const float4*>(Ws + kg * WS_STRIDE);

    unsigned long long acc[16];                 // [r*8 + jp]
#pragma unroll
    for (int i = 0; i < 16; i++) acc[i] = 0ull;

#pragma unroll
    for (int c = 0; c < 8; c++) {               // 8 chunks of 8 k
        float x8[2][8];
#pragma unroll
        for (int r = 0; r < 2; r++) {
            size_t base = (size_t)(row0 + r) * 128 + kg * 16 + c * 2;
            float4 a = __ldg(xv + base);
            float4 b = __ldg(xv + base + 1);
            x8[r][0]=a.x; x8[r][1]=a.y; x8[r][2]=a.z; x8[r][3]=a.w;
            x8[r][4]=b.x; x8[r][5]=b.y; x8[r][6]=b.z; x8[r][7]=b.w;
        }
#pragma unroll
        for (int ki = 0; ki < 8; ki++) {
            int kk = c * 8 + ki;
            float4 w0 = wsv[kk * 4 + 0];
            float4 w1 = wsv[kk * 4 + 1];
            float4 w2 = wsv[kk * 4 + 2];
            float4 w3 = wsv[kk * 4 + 3];
            unsigned long long wp[8];
            wp[0] = *reinterpret_cast<unsigned long long*>(&w0.x);
            wp[1] = *reinterpret_cast<unsigned long long*>(&w0.z);
            wp[2] = *reinterpret_cast<unsigned long long*>(&w1.x);
            wp[3] = *reinterpret_cast<unsigned long long*>(&w1.z);
            wp[4] = *reinterpret_cast<unsigned long long*>(&w2.x);
            wp[5] = *reinterpret_cast<unsigned long long*>(&w2.z);
            wp[6] = *reinterpret_cast<unsigned long long*>(&w3.x);
            wp[7] = *reinterpret_cast<unsigned long long*>(&w3.z);
#pragma unroll
            for (int r = 0; r < 2; r++) {
                unsigned long long xx;
                PACK2(xx, x8[r][ki]);
#pragma unroll
                for (int jp = 0; jp < 8; jp++)
                    FMA_F32X2(acc[r * 8 + jp], xx, wp[jp], acc[r * 8 + jp]);
            }
        }
    }

    // reduce over the 8 kg lanes (xor within 8-lane group)
#pragma unroll
    for (int off = 4; off >= 1; off >>= 1) {
#pragma unroll
        for (int i = 0; i < 16; i++) {
            unsigned long long o = __shfl_xor_sync(0xffffffffu, acc[i], off);
            ADD_F32X2(acc[i], acc[i], o);
        }
    }

    if (kg == 0) {
#pragma unroll
        for (int r = 0; r < 2; r++) {
            float4* o = reinterpret_cast<float4*>(g_h1 + (size_t)(row0 + r) * 16);
#pragma unroll
            for (int t = 0; t < 4; t++) {
                float2 lo = *reinterpret_cast<float2*>(&acc[r * 8 + t * 2]);
                float2 hi = *reinterpret_cast<float2*>(&acc[r * 8 + t * 2 + 1]);
                o[t] = make_float4(lo.x, lo.y, hi.x, hi.y);
            }
        }
    }
}

// ---------------------------------------------------------------------------
// 5) scan3: each block self-sums blksum[0..b-1], applies offset
// ---------------------------------------------------------------------------
__global__ void scan3_kernel() {
    __shared__ int sdata[256];
    int b = blockIdx.x, t = threadIdx.x;
    int s = 0;
    for (int i = t; i < b; i += 256) s += g_blksum[i];
    sdata[t] = s;
    __syncthreads();
#pragma unroll
    for (int off = 128; off >= 1; off >>= 1) {
        if (t < off) sdata[t] += sdata[t + off];
        __syncthreads();
    }
    int offset = sdata[0];
    int i = b * 256 + t;
    if (i < NNODES) {
        int r = g_rowptr[i] + offset;
        g_rowptr[i] = r;
        g_cursor[i] = r;
    }
    if (b == 0 && t == 0) g_rowptr[NNODES] = NEDGES;
}

// ---------------------------------------------------------------------------
// 6) fill CSR adjacency (src ids grouped by dst)
// ---------------------------------------------------------------------------
__global__ void fill_kernel(const int* __restrict__ ei, int E) {
    int e = blockIdx.x * blockDim.x + threadIdx.x;
    if (e >= E) return;
    int s = edge_at(ei, e, E, 0);
    int d = edge_at(ei, e, E, 1);
    int pos = atomicAdd(&g_cursor[d], 1);
    g_esrc[pos] = s;
}

// ---------------------------------------------------------------------------
// 7/8) CSR aggregation, warp per node, pure sums (relu+b1 once per node).
// ---------------------------------------------------------------------------
template <int LAYER>
__global__ void agg_kernel(const float* __restrict__ b1) {
    int warp = (blockIdx.x * blockDim.x + threadIdx.x) >> 5;
    if (warp >= NNODES) return;
    int lane = threadIdx.x & 31;
    int q = lane >> 3;
    int j = lane & 7;

    int start = __ldg(&g_rowptr[warp]);
    int end   = __ldg(&g_rowptr[warp + 1]);

    const float4* feat = reinterpret_cast<const float4*>(
        (LAYER == 1) ? g_h1 : g_h2);

    float4 acc = make_float4(0.f, 0.f, 0.f, 0.f);
    int e = start + j;
    for (; e + 8 < end; e += 16) {
        int s0 = __ldg(&g_esrc[e]);
        int s1 = __ldg(&g_esrc[e + 8]);
        float4 v0 = __ldg(feat + (size_t)s0 * 4 + q);
        float4 v1 = __ldg(feat + (size_t)s1 * 4 + q);
        acc.x += v0.x + v1.x; acc.y += v0.y + v1.y;
        acc.z += v0.z + v1.z; acc.w += v0.w + v1.w;
    }
    if (e < end) {
        int s = __ldg(&g_esrc[e]);
        float4 v = __ldg(feat + (size_t)s * 4 + q);
        acc.x += v.x; acc.y += v.y; acc.z += v.z; acc.w += v.w;
    }

#pragma unroll
    for (int off = 4; off >= 1; off >>= 1) {
        acc.x += __shfl_xor_sync(0xffffffffu, acc.x, off);
        acc.y += __shfl_xor_sync(0xffffffffu, acc.y, off);
        acc.z += __shfl_xor_sync(0xffffffffu, acc.z, off);
        acc.w += __shfl_xor_sync(0xffffffffu, acc.w, off);
    }

    if (j == 0) {
        if (LAYER == 1) {
            float4 bq = __ldg(reinterpret_cast<const float4*>(b1) + q);
            acc.x = fmaxf(acc.x + bq.x, 0.f);
            acc.y = fmaxf(acc.y + bq.y, 0.f);
            acc.z = fmaxf(acc.z + bq.z, 0.f);
            acc.w = fmaxf(acc.w + bq.w, 0.f);
            reinterpret_cast<float4*>(g_h2 + (size_t)warp * 16)[q] = acc;
        } else {
            reinterpret_cast<float4*>(g_agg2 + (size_t)warp * 16)[q] = acc;
        }
    }
}

// ---------------------------------------------------------------------------
// 9) out = log_softmax(g_agg2 @ W2 + b2)
// ---------------------------------------------------------------------------
__global__ void final_kernel(const float* __restrict__ W2,
                             const float* __restrict__ b2,
                             float* __restrict__ out) {
    int i = blockIdx.x * blockDim.x + threadIdx.x;
    if (i >= NNODES) return;

    float a[16];
    const float4* ap = reinterpret_cast<const float4*>(g_agg2 + (size_t)i * 16);
#pragma unroll
    for (int t = 0; t < 4; t++) {
        float4 v = ap[t];
        a[t * 4 + 0] = v.x; a[t * 4 + 1] = v.y;
        a[t * 4 + 2] = v.z; a[t * 4 + 3] = v.w;
    }

    float v[40];
#pragma unroll
    for (int j = 0; j < 40; j++) v[j] = __ldg(b2 + j);
#pragma unroll
    for (int k = 0; k < 16; k++) {
        float ak = a[k];
#pragma unroll
        for (int j = 0; j < 40; j++)
            v[j] = fmaf(ak, __ldg(W2 + k * 40 + j), v[j]);
    }

    float m = v[0];
#pragma unroll
    for (int j = 1; j < 40; j++) m = fmaxf(m, v[j]);
    float ssum = 0.f;
#pragma unroll
    for (int j = 0; j < 40; j++) ssum += expf(v[j] - m);
    float lse = m + logf(ssum);

    float4* op = reinterpret_cast<float4*>(out + (size_t)i * 40);
#pragma unroll
    for (int t = 0; t < 10; t++)
        op[t] = make_float4(v[t*4+0] - lse, v[t*4+1] - lse,
                            v[t*4+2] - lse, v[t*4+3] - lse);
}

// ---------------------------------------------------------------------------
extern "C" void kernel_launch(void* const* d_in, const int* in_sizes, int n_in,
                              void* d_out, int out_size) {
    const float* x  = nullptr;
    const int*   ei = nullptr;
    const float* W1 = nullptr;
    const float* b1 = nullptr;
    const float* W2 = nullptr;
    const float* b2 = nullptr;

    for (int i = 0; i < n_in; i++) {
        int sz = in_sizes[i];
        if      (sz == 51200000)                   x  = (const float*)d_in[i];
        else if (sz == 6400000 || sz == 12800000)  ei = (const int*)d_in[i];
        else if (sz == 8192)                       W1 = (const float*)d_in[i];
        else if (sz == 16)                         b1 = (const float*)d_in[i];
        else if (sz == 640)                        W2 = (const float*)d_in[i];
        else if (sz == 40)                         b2 = (const float*)d_in[i];
    }

    const int E = NEDGES;
    float* out = (float*)d_out;

    prep_kernel<<<NB_SCAN, 256>>>(ei);                        // 1
    hist_kernel<<<(E + 255) / 256, 256>>>(ei, E);             // 2
    scan1_kernel<<<NB_SCAN, 256>>>();                         // 3
    gemm1_kernel<<<3125, 128>>>(x, W1);                       // 4  <- profiled
    scan3_kernel<<<NB_SCAN, 256>>>();                         // 5
    fill_kernel<<<(E + 255) / 256, 256>>>(ei, E);             // 6
    agg_kernel<1><<<(NNODES * 32 + 255) / 256, 256>>>(b1);    // 7
    agg_kernel<2><<<(NNODES * 32 + 255) / 256, 256>>>(nullptr); // 8
    final_kernel<<<(NNODES + 127) / 128, 128>>>(W2, b2, out); // 9
}

// round 16
// speedup vs baseline: 1.0986x; 1.0986x over previous
#include <cuda_runtime.h>
#include <cstdint>

// ---------------------------------------------------------------------------
// N=100000, 512 -> 16 -> 40, E=3.2M int32 edges.
// out = log_softmax( segsum(relu(segsum((xW1)[src])+b1)[src]) @ W2 + b2 )
// (W2 hoisted past the scatter by linearity of segment_sum.)
//
// R16: gemm1 reads W from __constant__ memory with warp-uniform indices
// (LDCU, uniform-const port, floor 1) -- off the L1/LSU path that bound all
// smem variants (~104us, L1 80-90%). One row/thread, FFMA2 col-pairs,
// x via front-batched LDG.128. W staged by cudaMemcpyToSymbolAsync (D2D).
// Agg gather unrolled x4. RULE: device globals never passed as kernel args.
// ---------------------------------------------------------------------------

#define NNODES 100000
#define HID 16
#define NEDGES 3200000
#define NB_SCAN 391         // ceil(NNODES/256)

__constant__ __align__(16) float cW[8192];            // W1 [512][16]

__device__ __align__(16) float g_h1 [NNODES * HID];   // x @ W1
__device__ __align__(16) float g_h2 [NNODES * HID];   // relu(segsum(h1)+b1)
__device__ __align__(16) float g_agg2[NNODES * HID];  // segsum(h2)
__device__ int g_cnt   [NNODES];
__device__ int g_rowptr[NNODES + 1];
__device__ int g_cursor[NNODES];
__device__ int g_esrc  [NEDGES];
__device__ int g_blksum[NB_SCAN];
__device__ int g_is64;

// packed f32x2 ops (PTX-only)
#define FMA_F32X2(d, a, b, c) \
    asm("fma.rn.f32x2 %0, %1, %2, %3;" : "=l"(d) : "l"(a), "l"(b), "l"(c))
#define PACK2(d, s) \
    asm("mov.b64 %0, {%1, %1};" : "=l"(d) : "r"(__float_as_uint(s)))

// ---------------------------------------------------------------------------
__device__ __forceinline__ int edge_at(const int* ei, int idx, int E, int half) {
    if (g_is64) {
        const long long* ll = reinterpret_cast<const long long*>(ei);
        return (int)__ldg(ll + (size_t)half * E + idx);
    }
    return __ldg(ei + (size_t)half * E + idx);
}

// ---------------------------------------------------------------------------
// 1) prep: zero g_cnt; block 0 also detects int64 storage
// ---------------------------------------------------------------------------
__global__ void prep_kernel(const int* __restrict__ ei) {
    int i = blockIdx.x * blockDim.x + threadIdx.x;
    for (; i < NNODES; i += gridDim.x * blockDim.x) g_cnt[i] = 0;

    if (blockIdx.x == 0) {
        __shared__ int any_nonzero;
        if (threadIdx.x == 0) any_nonzero = 0;
        __syncthreads();
        int bad = 0;
        for (int w = 1 + 2 * threadIdx.x; w < 2048; w += 2 * blockDim.x)
            if (ei[w] != 0) bad = 1;
        if (bad) atomicOr(&any_nonzero, 1);
        __syncthreads();
        if (threadIdx.x == 0) g_is64 = (any_nonzero == 0) ? 1 : 0;
    }
}

// ---------------------------------------------------------------------------
// 2) histogram of destinations
// ---------------------------------------------------------------------------
__global__ void hist_kernel(const int* __restrict__ ei, int E) {
    int e = blockIdx.x * blockDim.x + threadIdx.x;
    if (e >= E) return;
    int d = edge_at(ei, e, E, 1);
    atomicAdd(&g_cnt[d], 1);
}

// ---------------------------------------------------------------------------
// 3) scan1: block-local exclusive scan; g_blksum[b] = block total
// ---------------------------------------------------------------------------
__global__ void scan1_kernel() {
    __shared__ int buf[2][256];
    int t = threadIdx.x, b = blockIdx.x;
    int i = b * 256 + t;
    int v = (i < NNODES) ? g_cnt[i] : 0;
    int cur = 0;
    buf[0][t] = v;
    __syncthreads();
#pragma unroll
    for (int off = 1; off < 256; off <<= 1) {
        int x = buf[cur][t];
        if (t >= off) x += buf[cur][t - off];
        buf[cur ^ 1][t] = x;
        cur ^= 1;
        __syncthreads();
    }
    int incl = buf[cur][t];
    if (i < NNODES) g_rowptr[i] = incl - v;
    if (t == 255) g_blksum[b] = incl;
}

// ---------------------------------------------------------------------------
// 4) h1 = x @ W1 — one row/thread; W from constant memory (warp-uniform
//    indices -> LDCU on the uniform-const port, zero L1 traffic for W).
//    FFMA2 over column pairs; x via 4 front-batched LDG.128 per 16-k chunk.
// ---------------------------------------------------------------------------
__global__ void __launch_bounds__(256) gemm1_kernel(const float* __restrict__ x) {
    int row = blockIdx.x * 256 + threadIdx.x;
    bool live = (row < NNODES);
    int r = live ? row : (NNODES - 1);

    const float4* xr = reinterpret_cast<const float4*>(x + (size_t)r * 512);
    const float4* w4 = reinterpret_cast<const float4*>(cW);

    unsigned long long acc[8];
#pragma unroll
    for (int i = 0; i < 8; i++) acc[i] = 0ull;

#pragma unroll 2
    for (int c = 0; c < 32; c++) {            // 32 chunks of 16 k
        float4 xv[4];
#pragma unroll
        for (int t = 0; t < 4; t++)
            xv[t] = __ldg(xr + c * 4 + t);

#pragma unroll
        for (int t = 0; t < 4; t++) {
            float xs[4] = {xv[t].x, xv[t].y, xv[t].z, xv[t].w};
#pragma unroll
            for (int d = 0; d < 4; d++) {
                int k = c * 16 + t * 4 + d;   // warp-uniform
                float4 wa = w4[k * 4 + 0];    // constant loads (LDCU)
                float4 wb = w4[k * 4 + 1];
                float4 wc = w4[k * 4 + 2];
                float4 wd = w4[k * 4 + 3];
                unsigned long long wp[8];
                wp[0] = *reinterpret_cast<unsigned long long*>(&wa.x);
                wp[1] = *reinterpret_cast<unsigned long long*>(&wa.z);
                wp[2] = *reinterpret_cast<unsigned long long*>(&wb.x);
                wp[3] = *reinterpret_cast<unsigned long long*>(&wb.z);
                wp[4] = *reinterpret_cast<unsigned long long*>(&wc.x);
                wp[5] = *reinterpret_cast<unsigned long long*>(&wc.z);
                wp[6] = *reinterpret_cast<unsigned long long*>(&wd.x);
                wp[7] = *reinterpret_cast<unsigned long long*>(&wd.z);
                unsigned long long xx;
                PACK2(xx, xs[d]);
#pragma unroll
                for (int jp = 0; jp < 8; jp++)
                    FMA_F32X2(acc[jp], xx, wp[jp], acc[jp]);
            }
        }
    }

    if (live) {
        float4* o = reinterpret_cast<float4*>(g_h1 + (size_t)row * 16);
#pragma unroll
        for (int t = 0; t < 4; t++) {
            float2 lo = *reinterpret_cast<float2*>(&acc[t * 2]);
            float2 hi = *reinterpret_cast<float2*>(&acc[t * 2 + 1]);
            o[t] = make_float4(lo.x, lo.y, hi.x, hi.y);
        }
    }
}

// ---------------------------------------------------------------------------
// 5) scan3: each block self-sums blksum[0..b-1], applies offset
// ---------------------------------------------------------------------------
__global__ void scan3_kernel() {
    __shared__ int sdata[256];
    int b = blockIdx.x, t = threadIdx.x;
    int s = 0;
    for (int i = t; i < b; i += 256) s += g_blksum[i];
    sdata[t] = s;
    __syncthreads();
#pragma unroll
    for (int off = 128; off >= 1; off >>= 1) {
        if (t < off) sdata[t] += sdata[t + off];
        __syncthreads();
    }
    int offset = sdata[0];
    int i = b * 256 + t;
    if (i < NNODES) {
        int r = g_rowptr[i] + offset;
        g_rowptr[i] = r;
        g_cursor[i] = r;
    }
    if (b == 0 && t == 0) g_rowptr[NNODES] = NEDGES;
}

// ---------------------------------------------------------------------------
// 6) fill CSR adjacency (src ids grouped by dst)
// ---------------------------------------------------------------------------
__global__ void fill_kernel(const int* __restrict__ ei, int E) {
    int e = blockIdx.x * blockDim.x + threadIdx.x;
    if (e >= E) return;
    int s = edge_at(ei, e, E, 0);
    int d = edge_at(ei, e, E, 1);
    int pos = atomicAdd(&g_cursor[d], 1);
    g_esrc[pos] = s;
}

// ---------------------------------------------------------------------------
// 7/8) CSR aggregation, warp per node, pure sums (relu+b1 once per node).
//      Gather unrolled x4 for memory-level parallelism.
// ---------------------------------------------------------------------------
template <int LAYER>
__global__ void agg_kernel(const float* __restrict__ b1) {
    int warp = (blockIdx.x * blockDim.x + threadIdx.x) >> 5;
    if (warp >= NNODES) return;
    int lane = threadIdx.x & 31;
    int q = lane >> 3;
    int j = lane & 7;

    int start = __ldg(&g_rowptr[warp]);
    int end   = __ldg(&g_rowptr[warp + 1]);

    const float4* feat = reinterpret_cast<const float4*>(
        (LAYER == 1) ? g_h1 : g_h2);

    float4 acc = make_float4(0.f, 0.f, 0.f, 0.f);
    int e = start + j;
    for (; e + 24 < end; e += 32) {
        int s0 = __ldg(&g_esrc[e]);
        int s1 = __ldg(&g_esrc[e + 8]);
        int s2 = __ldg(&g_esrc[e + 16]);
        int s3 = __ldg(&g_esrc[e + 24]);
        float4 v0 = __ldg(feat + (size_t)s0 * 4 + q);
        float4 v1 = __ldg(feat + (size_t)s1 * 4 + q);
        float4 v2 = __ldg(feat + (size_t)s2 * 4 + q);
        float4 v3 = __ldg(feat + (size_t)s3 * 4 + q);
        acc.x += (v0.x + v1.x) + (v2.x + v3.x);
        acc.y += (v0.y + v1.y) + (v2.y + v3.y);
        acc.z += (v0.z + v1.z) + (v2.z + v3.z);
        acc.w += (v0.w + v1.w) + (v2.w + v3.w);
    }
    for (; e < end; e += 8) {
        int s = __ldg(&g_esrc[e]);
        float4 v = __ldg(feat + (size_t)s * 4 + q);
        acc.x += v.x; acc.y += v.y; acc.z += v.z; acc.w += v.w;
    }

#pragma unroll
    for (int off = 4; off >= 1; off >>= 1) {
        acc.x += __shfl_xor_sync(0xffffffffu, acc.x, off);
        acc.y += __shfl_xor_sync(0xffffffffu, acc.y, off);
        acc.z += __shfl_xor_sync(0xffffffffu, acc.z, off);
        acc.w += __shfl_xor_sync(0xffffffffu, acc.w, off);
    }

    if (j == 0) {
        if (LAYER == 1) {
            float4 bq = __ldg(reinterpret_cast<const float4*>(b1) + q);
            acc.x = fmaxf(acc.x + bq.x, 0.f);
            acc.y = fmaxf(acc.y + bq.y, 0.f);
            acc.z = fmaxf(acc.z + bq.z, 0.f);
            acc.w = fmaxf(acc.w + bq.w, 0.f);
            reinterpret_cast<float4*>(g_h2 + (size_t)warp * 16)[q] = acc;
        } else {
            reinterpret_cast<float4*>(g_agg2 + (size_t)warp * 16)[q] = acc;
        }
    }
}

// ---------------------------------------------------------------------------
// 9) out = log_softmax(g_agg2 @ W2 + b2)
// ---------------------------------------------------------------------------
__global__ void final_kernel(const float* __restrict__ W2,
                             const float* __restrict__ b2,
                             float* __restrict__ out) {
    int i = blockIdx.x * blockDim.x + threadIdx.x;
    if (i >= NNODES) return;

    float a[16];
    const float4* ap = reinterpret_cast<const float4*>(g_agg2 + (size_t)i * 16);
#pragma unroll
    for (int t = 0; t < 4; t++) {
        float4 v = ap[t];
        a[t * 4 + 0] = v.x; a[t * 4 + 1] = v.y;
        a[t * 4 + 2] = v.z; a[t * 4 + 3] = v.w;
    }

    float v[40];
#pragma unroll
    for (int j = 0; j < 40; j++) v[j] = __ldg(b2 + j);
#pragma unroll
    for (int k = 0; k < 16; k++) {
        float ak = a[k];
#pragma unroll
        for (int j = 0; j < 40; j++)
            v[j] = fmaf(ak, __ldg(W2 + k * 40 + j), v[j]);
    }

    float m = v[0];
#pragma unroll
    for (int j = 1; j < 40; j++) m = fmaxf(m, v[j]);
    float ssum = 0.f;
#pragma unroll
    for (int j = 0; j < 40; j++) ssum += expf(v[j] - m);
    float lse = m + logf(ssum);

    float4* op = reinterpret_cast<float4*>(out + (size_t)i * 40);
#pragma unroll
    for (int t = 0; t < 10; t++)
        op[t] = make_float4(v[t*4+0] - lse, v[t*4+1] - lse,
                            v[t*4+2] - lse, v[t*4+3] - lse);
}

// ---------------------------------------------------------------------------
extern "C" void kernel_launch(void* const* d_in, const int* in_sizes, int n_in,
                              void* d_out, int out_size) {
    const float* x  = nullptr;
    const int*   ei = nullptr;
    const float* W1 = nullptr;
    const float* b1 = nullptr;
    const float* W2 = nullptr;
    const float* b2 = nullptr;

    for (int i = 0; i < n_in; i++) {
        int sz = in_sizes[i];
        if      (sz == 51200000)                   x  = (const float*)d_in[i];
        else if (sz == 6400000 || sz == 12800000)  ei = (const int*)d_in[i];
        else if (sz == 8192)                       W1 = (const float*)d_in[i];
        else if (sz == 16)                         b1 = (const float*)d_in[i];
        else if (sz == 640)                        W2 = (const float*)d_in[i];
        else if (sz == 40)                         b2 = (const float*)d_in[i];
    }

    const int E = NEDGES;
    float* out = (float*)d_out;

    // stage W1 into constant memory (async D2D memcpy node; capturable)
    cudaMemcpyToSymbolAsync(cW, W1, 8192 * sizeof(float), 0,
                            cudaMemcpyDeviceToDevice, 0);

    prep_kernel<<<NB_SCAN, 256>>>(ei);                        // k1
    hist_kernel<<<(E + 255) / 256, 256>>>(ei, E);             // k2
    scan1_kernel<<<NB_SCAN, 256>>>();                         // k3
    gemm1_kernel<<<391, 256>>>(x);                            // k4 <- profiled?
    scan3_kernel<<<NB_SCAN, 256>>>();                         // k5
    fill_kernel<<<(E + 255) / 256, 256>>>(ei, E);             // k6
    agg_kernel<1><<<(NNODES * 32 + 255) / 256, 256>>>(b1);    // k7
    agg_kernel<2><<<(NNODES * 32 + 255) / 256, 256>>>(nullptr); // k8
    final_kernel<<<(NNODES + 127) / 128, 128>>>(W2, b2, out); // k9
}